// round 7
// baseline (speedup 1.0000x reference)
#include <cuda_runtime.h>
#include <cuda_bf16.h>
#include <math.h>
#include <stdint.h>

// Problem constants
#define BATCH 2
#define SEQ 2048
#define TOK (BATCH*SEQ)          // 4096
#define HID 3584
#define NH 32
#define NKV 4
#define HD 128
#define QD (NH*HD)               // 4096
#define KVD (NKV*HD)             // 512

// fp32 scratch
__device__ float g_q[(size_t)TOK*QD];
__device__ float g_k[(size_t)TOK*KVD];
__device__ float g_v[(size_t)TOK*KVD];
// split-bf16 scratch
__device__ __nv_bfloat16 g_hh[(size_t)TOK*HID],  g_hl[(size_t)TOK*HID];
__device__ __nv_bfloat16 g_wqh[(size_t)QD*HID],  g_wql[(size_t)QD*HID];
__device__ __nv_bfloat16 g_wkh[(size_t)KVD*HID], g_wkl[(size_t)KVD*HID];
__device__ __nv_bfloat16 g_wvh[(size_t)KVD*HID], g_wvl[(size_t)KVD*HID];
__device__ __nv_bfloat16 g_woh[(size_t)HID*QD],  g_wol[(size_t)HID*QD];
__device__ __nv_bfloat16 g_ah[(size_t)TOK*QD],   g_al[(size_t)TOK*QD];
__device__ __nv_bfloat16 g_kh[(size_t)TOK*KVD],  g_kl[(size_t)TOK*KVD];
__device__ __nv_bfloat16 g_vh[(size_t)TOK*KVD],  g_vl[(size_t)TOK*KVD];

// ===========================================================================
// PTX helpers
// ===========================================================================
__device__ __forceinline__ uint32_t smem_u32(const void* p) {
    uint32_t a;
    asm("{ .reg .u64 t; cvta.to.shared.u64 t, %1; cvt.u32.u64 %0, t; }" : "=r"(a) : "l"(p));
    return a;
}
__device__ __forceinline__ void cp_async16(uint32_t dst, const void* src) {
    asm volatile("cp.async.cg.shared.global [%0], [%1], 16;" :: "r"(dst), "l"(src) : "memory");
}
#define CP_COMMIT() asm volatile("cp.async.commit_group;" ::: "memory")
#define CP_WAIT(n)  asm volatile("cp.async.wait_group %0;" :: "n"(n) : "memory")

__device__ __forceinline__ void ldm4(uint32_t* r, uint32_t addr) {
    asm volatile("ldmatrix.sync.aligned.m8n8.x4.shared.b16 {%0,%1,%2,%3}, [%4];"
                 : "=r"(r[0]), "=r"(r[1]), "=r"(r[2]), "=r"(r[3]) : "r"(addr));
}
__device__ __forceinline__ void ldm4t(uint32_t* r, uint32_t addr) {
    asm volatile("ldmatrix.sync.aligned.m8n8.x4.trans.shared.b16 {%0,%1,%2,%3}, [%4];"
                 : "=r"(r[0]), "=r"(r[1]), "=r"(r[2]), "=r"(r[3]) : "r"(addr));
}
__device__ __forceinline__ void mma_bf16(float* c, const uint32_t* a, const uint32_t* b) {
    asm volatile("mma.sync.aligned.m16n8k16.row.col.f32.bf16.bf16.f32 "
                 "{%0,%1,%2,%3}, {%4,%5,%6,%7}, {%8,%9}, {%0,%1,%2,%3};"
                 : "+f"(c[0]), "+f"(c[1]), "+f"(c[2]), "+f"(c[3])
                 : "r"(a[0]), "r"(a[1]), "r"(a[2]), "r"(a[3]), "r"(b[0]), "r"(b[1]));
}
__device__ __forceinline__ uint32_t cvt2bf(float hi, float lo) {
    uint32_t r;
    asm("cvt.rn.bf16x2.f32 %0, %1, %2;" : "=r"(r) : "f"(hi), "f"(lo));
    return r;
}
__device__ __forceinline__ float bfloF(uint32_t p) { return __int_as_float(p << 16); }
__device__ __forceinline__ float bfhiF(uint32_t p) { return __int_as_float(p & 0xffff0000u); }

// fast 2^t on the FMA pipe (no MUFU)
__device__ __forceinline__ float fast_exp2(float t) {
    t = fmaxf(t, -120.0f);
    float r = t + 12582912.0f;
    float n = r - 12582912.0f;
    float f = t - n;
    int   ni = __float_as_int(r);
    float p = 1.3392112e-3f;
    p = fmaf(p, f, 9.6183463e-3f);
    p = fmaf(p, f, 5.5503277e-2f);
    p = fmaf(p, f, 2.4022652e-1f);
    p = fmaf(p, f, 6.9314718e-1f);
    p = fmaf(p, f, 1.0f);
    return __int_as_float(__float_as_int(p) + (ni << 23));
}

// ===========================================================================
// Fused split: all five fp32->bf16(hi,lo) splits in one launch.
// Compile-time ranges: hidden, Wq, Wk, Wv, Wo.
// ===========================================================================
#define SPL_N0 (TOK*HID)                       // 14680064
#define SPL_N1 (SPL_N0 + QD*HID)               // 29360128
#define SPL_N2 (SPL_N1 + KVD*HID)              // 31195136
#define SPL_N3 (SPL_N2 + KVD*HID)              // 33030144
#define SPL_N4 (SPL_N3 + HID*QD)               // 47710208

__global__ void split_all_kernel(
    const float* __restrict__ x0, const float* __restrict__ x1,
    const float* __restrict__ x2, const float* __restrict__ x3,
    const float* __restrict__ x4,
    __nv_bfloat16* __restrict__ h0, __nv_bfloat16* __restrict__ l0,
    __nv_bfloat16* __restrict__ h1, __nv_bfloat16* __restrict__ l1,
    __nv_bfloat16* __restrict__ h2, __nv_bfloat16* __restrict__ l2,
    __nv_bfloat16* __restrict__ h3, __nv_bfloat16* __restrict__ l3,
    __nv_bfloat16* __restrict__ h4, __nv_bfloat16* __restrict__ l4)
{
    int i = blockIdx.x * 256 + threadIdx.x;
    if (i >= SPL_N4) return;
    const float* x; __nv_bfloat16 *h, *l; int off;
    if (i < SPL_N0)      { x = x0; h = h0; l = l0; off = i; }
    else if (i < SPL_N1) { x = x1; h = h1; l = l1; off = i - SPL_N0; }
    else if (i < SPL_N2) { x = x2; h = h2; l = l2; off = i - SPL_N1; }
    else if (i < SPL_N3) { x = x3; h = h3; l = l3; off = i - SPL_N2; }
    else                 { x = x4; h = h4; l = l4; off = i - SPL_N3; }
    float v = x[off];
    __nv_bfloat16 hv = __float2bfloat16(v);
    h[off] = hv;
    l[off] = __float2bfloat16(v - __bfloat162float(hv));
}

// plain split (V after projection)
__global__ void split_bf16_kernel(const float* __restrict__ x,
                                  __nv_bfloat16* __restrict__ hi,
                                  __nv_bfloat16* __restrict__ lo, int n)
{
    int i = blockIdx.x * 256 + threadIdx.x;
    if (i >= n) return;
    float v = x[i];
    __nv_bfloat16 h = __float2bfloat16(v);
    hi[i] = h;
    lo[i] = __float2bfloat16(v - __bfloat162float(h));
}

// ===========================================================================
// mma.sync split-bf16 GEMM core: C[M,N] = A[M,K]*B[N,K]^T, 128x256x32 tiles,
// 3-stage cp.async pipeline, 8 warps (2x4), warp 64x64, 3-term split product.
// ===========================================================================
#define TSTR 40
#define OFF_AH 0
#define OFF_AL (128*TSTR*2)                    // 10240
#define OFF_BH (2*128*TSTR*2)                  // 20480
#define OFF_BL (OFF_BH + 256*TSTR*2)           // 40960
#define STAGE_B (OFF_BL + 256*TSTR*2)          // 61440
#define GEMM_SMEM (3*STAGE_B)                  // 184320

__device__ __forceinline__ void gemm_issue_loads(
    uint32_t sstage, const __nv_bfloat16* pAh, const __nv_bfloat16* pAl,
    const __nv_bfloat16* pBh, const __nv_bfloat16* pBl, int K, int ko, int tid)
{
    #pragma unroll
    for (int i = 0; i < 2; i++) {               // A: 128 rows x 4 chunks
        int c = tid + (i << 8);
        int row = c >> 2, kc = c & 3;
        uint32_t dst = (uint32_t)(row * TSTR + kc * 8) * 2;
        size_t src = (size_t)row * K + ko + kc * 8;
        cp_async16(sstage + OFF_AH + dst, pAh + src);
        cp_async16(sstage + OFF_AL + dst, pAl + src);
    }
    #pragma unroll
    for (int i = 0; i < 4; i++) {               // B: 256 rows x 4 chunks
        int c = tid + (i << 8);
        int row = c >> 2, kc = c & 3;
        uint32_t dst = (uint32_t)(row * TSTR + kc * 8) * 2;
        size_t src = (size_t)row * K + ko + kc * 8;
        cp_async16(sstage + OFF_BH + dst, pBh + src);
        cp_async16(sstage + OFF_BL + dst, pBl + src);
    }
}

__device__ __forceinline__ void gemm_core(
    const __nv_bfloat16* __restrict__ pAh, const __nv_bfloat16* __restrict__ pAl,
    const __nv_bfloat16* __restrict__ pBh, const __nv_bfloat16* __restrict__ pBl,
    float* __restrict__ Ct, int N, int K, char* smem)
{
    uint32_t sbase = smem_u32(smem);
    const int tid  = threadIdx.x;
    const int lane = tid & 31;
    const int wid  = tid >> 5;
    const int wm   = wid >> 2;     // 0..1 (64 rows each)
    const int wn   = wid & 3;      // 0..3 (64 cols each)

    const uint32_t laneA = (uint32_t)((lane & 15) * TSTR + ((lane >> 4) << 3)) * 2;
    const uint32_t laneB = (uint32_t)(((lane & 7) + ((lane >> 4) << 3)) * TSTR
                                      + (((lane >> 3) & 1) << 3)) * 2;

    float acc[4][8][4];
    #pragma unroll
    for (int i = 0; i < 4; i++)
        #pragma unroll
        for (int j = 0; j < 8; j++)
            #pragma unroll
            for (int r = 0; r < 4; r++) acc[i][j][r] = 0.f;

    const int KT = K >> 5;   // assumed >= 2
    gemm_issue_loads(sbase, pAh, pAl, pBh, pBl, K, 0, tid);
    CP_COMMIT();
    gemm_issue_loads(sbase + STAGE_B, pAh, pAl, pBh, pBl, K, 32, tid);
    CP_COMMIT();

    int stage = 0;
    for (int kt = 0; kt < KT; kt++) {
        if (kt < KT - 1) { CP_WAIT(1); } else { CP_WAIT(0); }
        __syncthreads();

        uint32_t st = sbase + (uint32_t)stage * STAGE_B;
        #pragma unroll
        for (int kk = 0; kk < 2; kk++) {
            uint32_t ah[4][4], al[4][4];
            #pragma unroll
            for (int mi = 0; mi < 4; mi++) {
                uint32_t aoff = (uint32_t)(((wm * 64 + mi * 16) * TSTR + kk * 16) * 2);
                ldm4(ah[mi], st + OFF_AH + aoff + laneA);
                ldm4(al[mi], st + OFF_AL + aoff + laneA);
            }
            #pragma unroll
            for (int nj2 = 0; nj2 < 4; nj2++) {
                uint32_t boff = (uint32_t)(((wn * 64 + nj2 * 16) * TSTR + kk * 16) * 2);
                uint32_t rh[4], rl[4];
                ldm4(rh, st + OFF_BH + boff + laneB);
                ldm4(rl, st + OFF_BL + boff + laneB);
                #pragma unroll
                for (int mi = 0; mi < 4; mi++) {
                    mma_bf16(acc[mi][nj2*2],   ah[mi], rh);
                    mma_bf16(acc[mi][nj2*2],   ah[mi], rl);
                    mma_bf16(acc[mi][nj2*2],   al[mi], rh);
                    mma_bf16(acc[mi][nj2*2+1], ah[mi], rh + 2);
                    mma_bf16(acc[mi][nj2*2+1], ah[mi], rl + 2);
                    mma_bf16(acc[mi][nj2*2+1], al[mi], rh + 2);
                }
            }
        }

        if (kt + 2 < KT) {
            int ns = stage;                    // (kt+2)%3 == (kt-1)%3 == stage before inc
            ns = stage - 1; if (ns < 0) ns += 3;
            gemm_issue_loads(sbase + (uint32_t)ns * STAGE_B,
                             pAh, pAl, pBh, pBl, K, (kt + 2) << 5, tid);
            CP_COMMIT();
        }
        stage++; if (stage == 3) stage = 0;
    }

    const int g = lane >> 2, tg = lane & 3;
    #pragma unroll
    for (int mi = 0; mi < 4; mi++) {
        int row = wm * 64 + mi * 16 + g;
        #pragma unroll
        for (int nj = 0; nj < 8; nj++) {
            int col = wn * 64 + nj * 8 + tg * 2;
            float* p0 = Ct + (size_t)row * N + col;
            float* p1 = p0 + (size_t)8 * N;
            p0[0] = acc[mi][nj][0]; p0[1] = acc[mi][nj][1];
            p1[0] = acc[mi][nj][2]; p1[1] = acc[mi][nj][3];
        }
    }
}

// Fused Q/K/V projection: grid (20, TOK/128). bx 0-15: Q; 16-17: K; 18-19: V.
__global__ void __launch_bounds__(256, 1)
gemm_qkv(const __nv_bfloat16* __restrict__ hh, const __nv_bfloat16* __restrict__ hl,
         const __nv_bfloat16* __restrict__ wqh, const __nv_bfloat16* __restrict__ wql,
         const __nv_bfloat16* __restrict__ wkh, const __nv_bfloat16* __restrict__ wkl,
         const __nv_bfloat16* __restrict__ wvh, const __nv_bfloat16* __restrict__ wvl,
         float* __restrict__ qb, float* __restrict__ kb, float* __restrict__ vb)
{
    extern __shared__ char smem[];
    const int bx = blockIdx.x;
    const int bm = blockIdx.y << 7;
    const __nv_bfloat16 *bhp, *blp;
    float* C; int bn, N;
    if (bx < 16)      { bhp = wqh; blp = wql; C = qb; bn = bx << 8;        N = QD;  }
    else if (bx < 18) { bhp = wkh; blp = wkl; C = kb; bn = (bx - 16) << 8; N = KVD; }
    else              { bhp = wvh; blp = wvl; C = vb; bn = (bx - 18) << 8; N = KVD; }
    gemm_core(hh + (size_t)bm * HID, hl + (size_t)bm * HID,
              bhp + (size_t)bn * HID, blp + (size_t)bn * HID,
              C + (size_t)bm * N + bn, N, HID, smem);
}

// Generic NT split GEMM (O-projection)
__global__ void __launch_bounds__(256, 1)
gemm_nt_split(const __nv_bfloat16* __restrict__ Ah, const __nv_bfloat16* __restrict__ Al,
              const __nv_bfloat16* __restrict__ Bh, const __nv_bfloat16* __restrict__ Bl,
              float* __restrict__ C, int N, int K)
{
    extern __shared__ char smem[];
    const int bm = blockIdx.y << 7;
    const int bn = blockIdx.x << 8;
    gemm_core(Ah + (size_t)bm * K, Al + (size_t)bm * K,
              Bh + (size_t)bn * K, Bl + (size_t)bn * K,
              C + (size_t)bm * N + bn, N, K, smem);
}

// ---------------------------------------------------------------------------
// RoPE on Q (fp32 in place). position_ids dtype probed (int32 vs int64).
// ---------------------------------------------------------------------------
__global__ void rope_kernel(float* __restrict__ X, const int* __restrict__ pos32,
                            int n_heads, int total)
{
    int idx = blockIdx.x * 256 + threadIdx.x;
    if (idx >= total) return;
    int d  = idx & 63;
    int r  = idx >> 6;
    int hh = r % n_heads;
    int t  = r / n_heads;
    bool is64 = (pos32[1] == 0);
    int p = is64 ? pos32[2 * t] : pos32[t];
    float invf = powf(1.0e6f, -(float)d * (1.0f / 64.0f));
    float fr = (float)p * invf;
    float sv, cv;
    sincosf(fr, &sv, &cv);
    float* xp = X + (size_t)t * (n_heads * 128) + hh * 128 + d;
    float x1 = xp[0], x2 = xp[64];
    xp[0]  = x1 * cv - x2 * sv;
    xp[64] = x2 * cv + x1 * sv;
}

// RoPE on K fused with hi/lo bf16 split
__global__ void rope_split_kernel(const float* __restrict__ X, const int* __restrict__ pos32,
                                  __nv_bfloat16* __restrict__ oh, __nv_bfloat16* __restrict__ ol,
                                  int n_heads, int total)
{
    int idx = blockIdx.x * 256 + threadIdx.x;
    if (idx >= total) return;
    int d  = idx & 63;
    int r  = idx >> 6;
    int hh = r % n_heads;
    int t  = r / n_heads;
    bool is64 = (pos32[1] == 0);
    int p = is64 ? pos32[2 * t] : pos32[t];
    float invf = powf(1.0e6f, -(float)d * (1.0f / 64.0f));
    float fr = (float)p * invf;
    float sv, cv;
    sincosf(fr, &sv, &cv);
    size_t off = (size_t)t * (n_heads * 128) + hh * 128 + d;
    float x1 = X[off], x2 = X[off + 64];
    float y1 = x1 * cv - x2 * sv;
    float y2 = x2 * cv + x1 * sv;
    __nv_bfloat16 h1 = __float2bfloat16(y1);
    __nv_bfloat16 h2 = __float2bfloat16(y2);
    oh[off]      = h1; ol[off]      = __float2bfloat16(y1 - __bfloat162float(h1));
    oh[off + 64] = h2; ol[off + 64] = __float2bfloat16(y2 - __bfloat162float(h2));
}

// ===========================================================================
// Flash attention: mma.sync split-bf16, FMA-pipe exp2, non-causal.
// Epilogue writes split bf16 hi/lo directly (feeds O-projection).
// ===========================================================================
#define FSTR 136
#define FA_Q_B (128*FSTR*2)
#define FA_T_B (64*FSTR*2)
#define FA_ST_B (4*FA_T_B)
#define FA_SMEM (2*FA_Q_B + 2*FA_ST_B)    // 208896

__device__ __forceinline__ void fa_load_kv(
    uint32_t stage, const __nv_bfloat16* __restrict__ Kh, const __nv_bfloat16* __restrict__ Kl,
    const __nv_bfloat16* __restrict__ Vh, const __nv_bfloat16* __restrict__ Vl,
    size_t rowbase, int kvoff, int tid)
{
    #pragma unroll
    for (int comp = 0; comp < 4; comp++) {
        const __nv_bfloat16* g = (comp == 0) ? Kh : (comp == 1) ? Kl : (comp == 2) ? Vh : Vl;
        #pragma unroll
        for (int jj = 0; jj < 4; jj++) {
            int cc = tid + (jj << 8);
            int row = cc >> 4, kc = cc & 15;
            cp_async16(stage + comp * FA_T_B + (uint32_t)(row * 272 + kc * 16),
                       g + (rowbase + row) * KVD + kvoff + kc * 8);
        }
    }
}

__global__ void __launch_bounds__(256, 1)
flash_attn_mma(const float* __restrict__ Q,
               const __nv_bfloat16* __restrict__ Kh, const __nv_bfloat16* __restrict__ Kl,
               const __nv_bfloat16* __restrict__ Vh, const __nv_bfloat16* __restrict__ Vl,
               __nv_bfloat16* __restrict__ ah, __nv_bfloat16* __restrict__ al)
{
    extern __shared__ char smem[];
    uint32_t sb = smem_u32(smem);
    const uint32_t sQH = sb;
    const uint32_t sQL = sb + FA_Q_B;
    const uint32_t sST = sb + 2 * FA_Q_B;

    const int tid = threadIdx.x, lane = tid & 31, w = tid >> 5;
    const int bh = blockIdx.y, b = bh >> 5, h = bh & 31, kvh = h >> 3;
    const int q0 = blockIdx.x << 7;
    const int g = lane >> 2, t = lane & 3;

    const float qsc = 0.08838834764831843f * 1.4426950408889634f;
    const float* Qg = Q + (size_t)(b * SEQ + q0) * QD + h * HD;
    #pragma unroll
    for (int i = 0; i < 16; i++) {
        int idx = tid + (i << 8);
        int row = idx >> 5, col = (idx & 31) << 2;
        float4 qv = *(const float4*)(Qg + (size_t)row * QD + col);
        float a0 = qv.x * qsc, a1 = qv.y * qsc, a2 = qv.z * qsc, a3 = qv.w * qsc;
        uint32_t h01 = cvt2bf(a1, a0);
        uint32_t h23 = cvt2bf(a3, a2);
        float r0 = a0 - bfloF(h01), r1 = a1 - bfhiF(h01);
        float r2 = a2 - bfloF(h23), r3 = a3 - bfhiF(h23);
        uint32_t l01 = cvt2bf(r1, r0);
        uint32_t l23 = cvt2bf(r3, r2);
        uint32_t doff = (uint32_t)(row * 272 + col * 2);
        *(uint2*)(smem + (sQH - sb) + doff) = make_uint2(h01, h23);
        *(uint2*)(smem + (sQL - sb) + doff) = make_uint2(l01, l23);
    }

    float m0 = -1e30f, m1 = -1e30f, l0 = 0.f, l1 = 0.f;
    float o[16][4];
    #pragma unroll
    for (int nd = 0; nd < 16; nd++)
        #pragma unroll
        for (int c = 0; c < 4; c++) o[nd][c] = 0.f;

    const size_t kvbase = (size_t)b * SEQ;
    const int kvoff = kvh * HD;

    const uint32_t lA = (uint32_t)(((lane & 15) * FSTR + ((lane >> 4) << 3)) * 2);
    const uint32_t lB = (uint32_t)((((lane & 7) + ((lane >> 4) << 3)) * FSTR
                                    + (((lane >> 3) & 1) << 3)) * 2);
    const uint32_t lV = (uint32_t)((((lane & 7) + (((lane >> 3) & 1) << 3)) * FSTR
                                    + (((lane >> 4) & 1) << 3)) * 2);

    fa_load_kv(sST, Kh, Kl, Vh, Vl, kvbase, kvoff, tid);
    CP_COMMIT();

    for (int kt = 0; kt < SEQ / 64; kt++) {
        if (kt + 1 < SEQ / 64) {
            fa_load_kv(sST + ((kt + 1) & 1) * FA_ST_B, Kh, Kl, Vh, Vl,
                       kvbase + (size_t)(kt + 1) * 64, kvoff, tid);
            CP_COMMIT();
            CP_WAIT(1);
        } else {
            CP_WAIT(0);
        }
        __syncthreads();

        const uint32_t st = sST + (kt & 1) * FA_ST_B;
        const uint32_t sKH = st, sKL = st + FA_T_B, sVH = st + 2*FA_T_B, sVL = st + 3*FA_T_B;

        float s[8][4];
        #pragma unroll
        for (int j = 0; j < 8; j++)
            #pragma unroll
            for (int c = 0; c < 4; c++) s[j][c] = 0.f;

        #pragma unroll
        for (int kk = 0; kk < 8; kk++) {
            uint32_t qh[4], ql[4];
            uint32_t qoff = (uint32_t)((w * 16 * FSTR + kk * 16) * 2);
            ldm4(qh, sQH + qoff + lA);
            ldm4(ql, sQL + qoff + lA);
            #pragma unroll
            for (int nj2 = 0; nj2 < 4; nj2++) {
                uint32_t koff = (uint32_t)((nj2 * 16 * FSTR + kk * 16) * 2);
                uint32_t rh[4], rl[4];
                ldm4(rh, sKH + koff + lB);
                ldm4(rl, sKL + koff + lB);
                mma_bf16(s[nj2*2],   qh, rh);     mma_bf16(s[nj2*2],   qh, rl);
                mma_bf16(s[nj2*2],   ql, rh);
                mma_bf16(s[nj2*2+1], qh, rh + 2); mma_bf16(s[nj2*2+1], qh, rl + 2);
                mma_bf16(s[nj2*2+1], ql, rh + 2);
            }
        }

        float mx0 = -1e30f, mx1 = -1e30f;
        #pragma unroll
        for (int j = 0; j < 8; j++) {
            mx0 = fmaxf(mx0, fmaxf(s[j][0], s[j][1]));
            mx1 = fmaxf(mx1, fmaxf(s[j][2], s[j][3]));
        }
        mx0 = fmaxf(mx0, __shfl_xor_sync(0xffffffffu, mx0, 1));
        mx0 = fmaxf(mx0, __shfl_xor_sync(0xffffffffu, mx0, 2));
        mx1 = fmaxf(mx1, __shfl_xor_sync(0xffffffffu, mx1, 1));
        mx1 = fmaxf(mx1, __shfl_xor_sync(0xffffffffu, mx1, 2));
        float mn0 = fmaxf(m0, mx0), mn1 = fmaxf(m1, mx1);
        float al0 = fast_exp2(m0 - mn0), al1 = fast_exp2(m1 - mn1);
        m0 = mn0; m1 = mn1;

        uint32_t ph[4][4], pl[4][4];
        float sum0 = 0.f, sum1 = 0.f;
        #pragma unroll
        for (int j = 0; j < 8; j++) {
            float p00 = fast_exp2(s[j][0] - mn0);
            float p01 = fast_exp2(s[j][1] - mn0);
            float p10 = fast_exp2(s[j][2] - mn1);
            float p11 = fast_exp2(s[j][3] - mn1);
            sum0 += p00 + p01; sum1 += p10 + p11;
            uint32_t hA = cvt2bf(p01, p00);
            uint32_t hB = cvt2bf(p11, p10);
            uint32_t lAp = cvt2bf(p01 - bfhiF(hA), p00 - bfloF(hA));
            uint32_t lBp = cvt2bf(p11 - bfhiF(hB), p10 - bfloF(hB));
            int kk2 = j >> 1, hf = (j & 1) << 1;
            ph[kk2][hf]     = hA;  ph[kk2][hf + 1] = hB;
            pl[kk2][hf]     = lAp; pl[kk2][hf + 1] = lBp;
        }
        sum0 += __shfl_xor_sync(0xffffffffu, sum0, 1);
        sum0 += __shfl_xor_sync(0xffffffffu, sum0, 2);
        sum1 += __shfl_xor_sync(0xffffffffu, sum1, 1);
        sum1 += __shfl_xor_sync(0xffffffffu, sum1, 2);
        l0 = l0 * al0 + sum0;
        l1 = l1 * al1 + sum1;
        #pragma unroll
        for (int nd = 0; nd < 16; nd++) {
            o[nd][0] *= al0; o[nd][1] *= al0;
            o[nd][2] *= al1; o[nd][3] *= al1;
        }

        #pragma unroll
        for (int kk2 = 0; kk2 < 4; kk2++) {
            #pragma unroll
            for (int ndp = 0; ndp < 8; ndp++) {
                uint32_t voff = (uint32_t)((kk2 * 16 * FSTR + ndp * 16) * 2);
                uint32_t vh[4], vl[4];
                ldm4t(vh, sVH + voff + lV);
                ldm4t(vl, sVL + voff + lV);
                mma_bf16(o[ndp*2],   ph[kk2], vh);     mma_bf16(o[ndp*2],   ph[kk2], vl);
                mma_bf16(o[ndp*2],   pl[kk2], vh);
                mma_bf16(o[ndp*2+1], ph[kk2], vh + 2); mma_bf16(o[ndp*2+1], ph[kk2], vl + 2);
                mma_bf16(o[ndp*2+1], pl[kk2], vh + 2);
            }
        }
        __syncthreads();
    }

    float il0 = 1.f / l0, il1 = 1.f / l1;
    size_t rbase = (size_t)(b * SEQ + q0 + w * 16 + g) * QD + h * HD;
    __nv_bfloat16* AH = ah + rbase;
    __nv_bfloat16* AL = al + rbase;
    #pragma unroll
    for (int nd = 0; nd < 16; nd++) {
        int col = nd * 8 + t * 2;
        float a0 = o[nd][0] * il0, a1 = o[nd][1] * il0;
        uint32_t hp = cvt2bf(a1, a0);
        uint32_t lp = cvt2bf(a1 - bfhiF(hp), a0 - bfloF(hp));
        *(uint32_t*)(AH + col) = hp;
        *(uint32_t*)(AL + col) = lp;
        float b0 = o[nd][2] * il1, b1 = o[nd][3] * il1;
        hp = cvt2bf(b1, b0);
        lp = cvt2bf(b1 - bfhiF(hp), b0 - bfloF(hp));
        *(uint32_t*)(AH + (size_t)8 * QD + col) = hp;
        *(uint32_t*)(AL + (size_t)8 * QD + col) = lp;
    }
}

// ---------------------------------------------------------------------------
extern "C" void kernel_launch(void* const* d_in, const int* in_sizes, int n_in,
                              void* d_out, int out_size)
{
    const float* hidden = (const float*)d_in[0];
    const int*   pos    = (const int*)d_in[1];
    const float* Wq     = (const float*)d_in[2];
    const float* Wk     = (const float*)d_in[3];
    const float* Wv     = (const float*)d_in[4];
    const float* Wo     = (const float*)d_in[5];
    float*       out    = (float*)d_out;

    float *qb, *kb, *vb;
    cudaGetSymbolAddress((void**)&qb, g_q);
    cudaGetSymbolAddress((void**)&kb, g_k);
    cudaGetSymbolAddress((void**)&vb, g_v);
    __nv_bfloat16 *hh,*hl,*wqh,*wql,*wkh,*wkl,*wvh,*wvl,*woh,*wol,*ah,*al,*kh,*kl,*vh,*vl;
    cudaGetSymbolAddress((void**)&hh,  g_hh);  cudaGetSymbolAddress((void**)&hl,  g_hl);
    cudaGetSymbolAddress((void**)&wqh, g_wqh); cudaGetSymbolAddress((void**)&wql, g_wql);
    cudaGetSymbolAddress((void**)&wkh, g_wkh); cudaGetSymbolAddress((void**)&wkl, g_wkl);
    cudaGetSymbolAddress((void**)&wvh, g_wvh); cudaGetSymbolAddress((void**)&wvl, g_wvl);
    cudaGetSymbolAddress((void**)&woh, g_woh); cudaGetSymbolAddress((void**)&wol, g_wol);
    cudaGetSymbolAddress((void**)&ah,  g_ah);  cudaGetSymbolAddress((void**)&al,  g_al);
    cudaGetSymbolAddress((void**)&kh,  g_kh);  cudaGetSymbolAddress((void**)&kl,  g_kl);
    cudaGetSymbolAddress((void**)&vh,  g_vh);  cudaGetSymbolAddress((void**)&vl,  g_vl);

    cudaFuncSetAttribute(gemm_qkv, cudaFuncAttributeMaxDynamicSharedMemorySize, GEMM_SMEM);
    cudaFuncSetAttribute(gemm_nt_split, cudaFuncAttributeMaxDynamicSharedMemorySize, GEMM_SMEM);
    cudaFuncSetAttribute(flash_attn_mma, cudaFuncAttributeMaxDynamicSharedMemorySize, FA_SMEM);

    // All input/weight splits in one launch
    split_all_kernel<<<(SPL_N4 + 255)/256, 256>>>(hidden, Wq, Wk, Wv, Wo,
                                                  hh, hl, wqh, wql, wkh, wkl,
                                                  wvh, wvl, woh, wol);

    // Fused Q/K/V projections (128x256 tiles)
    gemm_qkv<<<dim3(20, TOK/128), 256, GEMM_SMEM>>>(hh, hl, wqh, wql, wkh, wkl, wvh, wvl,
                                                    qb, kb, vb);

    // RoPE: Q in-place fp32; K fused rope+split; V plain split
    rope_kernel<<<(TOK*NH*64 + 255)/256, 256>>>(qb, pos, NH, TOK*NH*64);
    rope_split_kernel<<<(TOK*NKV*64 + 255)/256, 256>>>(kb, pos, kh, kl, NKV, TOK*NKV*64);
    split_bf16_kernel<<<((size_t)TOK*KVD + 255)/256, 256>>>(vb, vh, vl, TOK*KVD);

    // Flash attention -> split bf16 output
    flash_attn_mma<<<dim3(SEQ/128, BATCH*NH), 256, FA_SMEM>>>(qb, kh, kl, vh, vl, ah, al);

    // O projection (128x256 tiles)
    gemm_nt_split<<<dim3(HID/256, TOK/128), 256, GEMM_SMEM>>>(ah, al, woh, wol, out, HID, QD);
}

// round 8
// speedup vs baseline: 1.0000x; 1.0000x over previous
#include <cuda_runtime.h>
#include <cuda_bf16.h>
#include <math.h>
#include <stdint.h>

// Problem constants
#define BATCH 2
#define SEQ 2048
#define TOK (BATCH*SEQ)          // 4096
#define HID 3584
#define NH 32
#define NKV 4
#define HD 128
#define QD (NH*HD)               // 4096
#define KVD (NKV*HD)             // 512

// fp32 scratch
__device__ float g_q[(size_t)TOK*QD];
__device__ float g_k[(size_t)TOK*KVD];
__device__ float g_v[(size_t)TOK*KVD];
// split-bf16 scratch
__device__ __nv_bfloat16 g_hh[(size_t)TOK*HID],  g_hl[(size_t)TOK*HID];
__device__ __nv_bfloat16 g_wqh[(size_t)QD*HID],  g_wql[(size_t)QD*HID];
__device__ __nv_bfloat16 g_wkh[(size_t)KVD*HID], g_wkl[(size_t)KVD*HID];
__device__ __nv_bfloat16 g_wvh[(size_t)KVD*HID], g_wvl[(size_t)KVD*HID];
__device__ __nv_bfloat16 g_woh[(size_t)HID*QD],  g_wol[(size_t)HID*QD];
__device__ __nv_bfloat16 g_ah[(size_t)TOK*QD],   g_al[(size_t)TOK*QD];
__device__ __nv_bfloat16 g_kh[(size_t)TOK*KVD],  g_kl[(size_t)TOK*KVD];
__device__ __nv_bfloat16 g_vh[(size_t)TOK*KVD],  g_vl[(size_t)TOK*KVD];

// ===========================================================================
// PTX helpers
// ===========================================================================
__device__ __forceinline__ uint32_t smem_u32(const void* p) {
    uint32_t a;
    asm("{ .reg .u64 t; cvta.to.shared.u64 t, %1; cvt.u32.u64 %0, t; }" : "=r"(a) : "l"(p));
    return a;
}
__device__ __forceinline__ void cp_async16(uint32_t dst, const void* src) {
    asm volatile("cp.async.cg.shared.global [%0], [%1], 16;" :: "r"(dst), "l"(src) : "memory");
}
#define CP_COMMIT() asm volatile("cp.async.commit_group;" ::: "memory")
#define CP_WAIT(n)  asm volatile("cp.async.wait_group %0;" :: "n"(n) : "memory")

__device__ __forceinline__ void ldm4(uint32_t* r, uint32_t addr) {
    asm volatile("ldmatrix.sync.aligned.m8n8.x4.shared.b16 {%0,%1,%2,%3}, [%4];"
                 : "=r"(r[0]), "=r"(r[1]), "=r"(r[2]), "=r"(r[3]) : "r"(addr));
}
__device__ __forceinline__ void ldm4t(uint32_t* r, uint32_t addr) {
    asm volatile("ldmatrix.sync.aligned.m8n8.x4.trans.shared.b16 {%0,%1,%2,%3}, [%4];"
                 : "=r"(r[0]), "=r"(r[1]), "=r"(r[2]), "=r"(r[3]) : "r"(addr));
}
__device__ __forceinline__ void mma_bf16(float* c, const uint32_t* a, const uint32_t* b) {
    asm volatile("mma.sync.aligned.m16n8k16.row.col.f32.bf16.bf16.f32 "
                 "{%0,%1,%2,%3}, {%4,%5,%6,%7}, {%8,%9}, {%0,%1,%2,%3};"
                 : "+f"(c[0]), "+f"(c[1]), "+f"(c[2]), "+f"(c[3])
                 : "r"(a[0]), "r"(a[1]), "r"(a[2]), "r"(a[3]), "r"(b[0]), "r"(b[1]));
}
__device__ __forceinline__ uint32_t cvt2bf(float hi, float lo) {
    uint32_t r;
    asm("cvt.rn.bf16x2.f32 %0, %1, %2;" : "=r"(r) : "f"(hi), "f"(lo));
    return r;
}
__device__ __forceinline__ float bfloF(uint32_t p) { return __int_as_float(p << 16); }
__device__ __forceinline__ float bfhiF(uint32_t p) { return __int_as_float(p & 0xffff0000u); }

// fast 2^t on the FMA pipe (no MUFU)
__device__ __forceinline__ float fast_exp2(float t) {
    t = fmaxf(t, -120.0f);
    float r = t + 12582912.0f;
    float n = r - 12582912.0f;
    float f = t - n;
    int   ni = __float_as_int(r);
    float p = 1.3392112e-3f;
    p = fmaf(p, f, 9.6183463e-3f);
    p = fmaf(p, f, 5.5503277e-2f);
    p = fmaf(p, f, 2.4022652e-1f);
    p = fmaf(p, f, 6.9314718e-1f);
    p = fmaf(p, f, 1.0f);
    return __int_as_float(__float_as_int(p) + (ni << 23));
}

// ===========================================================================
// Fused split: all five fp32->bf16(hi,lo) splits in one launch.
// ===========================================================================
#define SPL_N0 (TOK*HID)
#define SPL_N1 (SPL_N0 + QD*HID)
#define SPL_N2 (SPL_N1 + KVD*HID)
#define SPL_N3 (SPL_N2 + KVD*HID)
#define SPL_N4 (SPL_N3 + HID*QD)

__global__ void split_all_kernel(
    const float* __restrict__ x0, const float* __restrict__ x1,
    const float* __restrict__ x2, const float* __restrict__ x3,
    const float* __restrict__ x4,
    __nv_bfloat16* __restrict__ h0, __nv_bfloat16* __restrict__ l0,
    __nv_bfloat16* __restrict__ h1, __nv_bfloat16* __restrict__ l1,
    __nv_bfloat16* __restrict__ h2, __nv_bfloat16* __restrict__ l2,
    __nv_bfloat16* __restrict__ h3, __nv_bfloat16* __restrict__ l3,
    __nv_bfloat16* __restrict__ h4, __nv_bfloat16* __restrict__ l4)
{
    int i = blockIdx.x * 256 + threadIdx.x;
    if (i >= SPL_N4) return;
    const float* x; __nv_bfloat16 *h, *l; int off;
    if (i < SPL_N0)      { x = x0; h = h0; l = l0; off = i; }
    else if (i < SPL_N1) { x = x1; h = h1; l = l1; off = i - SPL_N0; }
    else if (i < SPL_N2) { x = x2; h = h2; l = l2; off = i - SPL_N1; }
    else if (i < SPL_N3) { x = x3; h = h3; l = l3; off = i - SPL_N2; }
    else                 { x = x4; h = h4; l = l4; off = i - SPL_N3; }
    float v = x[off];
    __nv_bfloat16 hv = __float2bfloat16(v);
    h[off] = hv;
    l[off] = __float2bfloat16(v - __bfloat162float(hv));
}

// ===========================================================================
// prep_kv: K rope+split and V split in one launch (range dispatch).
// ===========================================================================
#define PK_N0 (TOK*NKV*64)              // K rope pair items
#define PK_N1 (PK_N0 + TOK*KVD)         // + V elements

__global__ void prep_kv(const float* __restrict__ kb, const float* __restrict__ vb,
                        const int* __restrict__ pos32,
                        __nv_bfloat16* __restrict__ kh, __nv_bfloat16* __restrict__ kl,
                        __nv_bfloat16* __restrict__ vh, __nv_bfloat16* __restrict__ vl)
{
    int i = blockIdx.x * 256 + threadIdx.x;
    if (i >= PK_N1) return;
    if (i < PK_N0) {
        int d  = i & 63;
        int r  = i >> 6;
        int hh = r % NKV;
        int t  = r / NKV;
        bool is64 = (pos32[1] == 0);
        int p = is64 ? pos32[2 * t] : pos32[t];
        float invf = powf(1.0e6f, -(float)d * (1.0f / 64.0f));
        float fr = (float)p * invf;
        float sv, cv;
        sincosf(fr, &sv, &cv);
        size_t off = (size_t)t * KVD + hh * 128 + d;
        float x1 = kb[off], x2 = kb[off + 64];
        float y1 = x1 * cv - x2 * sv;
        float y2 = x2 * cv + x1 * sv;
        __nv_bfloat16 h1 = __float2bfloat16(y1);
        __nv_bfloat16 h2 = __float2bfloat16(y2);
        kh[off]      = h1; kl[off]      = __float2bfloat16(y1 - __bfloat162float(h1));
        kh[off + 64] = h2; kl[off + 64] = __float2bfloat16(y2 - __bfloat162float(h2));
    } else {
        int j = i - PK_N0;
        float v = vb[j];
        __nv_bfloat16 h = __float2bfloat16(v);
        vh[j] = h;
        vl[j] = __float2bfloat16(v - __bfloat162float(h));
    }
}

// ===========================================================================
// mma.sync split-bf16 GEMM core (R6 config): 128x128x32 tiles, 4-stage
// cp.async pipeline, 8 warps (2x4), warp 64x32, 3-term split product.
// ===========================================================================
#define TSTR 40
#define TILE_B (128*TSTR*2)           // 10240
#define STAGE_B (4*TILE_B)            // 40960
#define GEMM_SMEM (4*STAGE_B)         // 163840

__device__ __forceinline__ void gemm_issue_loads(
    uint32_t sstage, const __nv_bfloat16* pAh, const __nv_bfloat16* pAl,
    const __nv_bfloat16* pBh, const __nv_bfloat16* pBl, int K, int ko, int tid)
{
    #pragma unroll
    for (int i = 0; i < 2; i++) {
        int c = tid + (i << 8);
        int row = c >> 2;
        int kc  = c & 3;
        uint32_t dst = (uint32_t)(row * TSTR + kc * 8) * 2;
        size_t src = (size_t)row * K + ko + kc * 8;
        cp_async16(sstage + 0*TILE_B + dst, pAh + src);
        cp_async16(sstage + 1*TILE_B + dst, pAl + src);
        cp_async16(sstage + 2*TILE_B + dst, pBh + src);
        cp_async16(sstage + 3*TILE_B + dst, pBl + src);
    }
}

__device__ __forceinline__ void gemm_core(
    const __nv_bfloat16* __restrict__ pAh, const __nv_bfloat16* __restrict__ pAl,
    const __nv_bfloat16* __restrict__ pBh, const __nv_bfloat16* __restrict__ pBl,
    float* __restrict__ Ct, int N, int K, char* smem)
{
    uint32_t sbase = smem_u32(smem);
    const int tid  = threadIdx.x;
    const int lane = tid & 31;
    const int wid  = tid >> 5;
    const int wm   = wid >> 2;
    const int wn   = wid & 3;

    const uint32_t laneA = (uint32_t)((lane & 15) * TSTR + ((lane >> 4) << 3)) * 2;
    const uint32_t laneB = (uint32_t)(((lane & 7) + ((lane >> 4) << 3)) * TSTR
                                      + (((lane >> 3) & 1) << 3)) * 2;

    float acc[4][4][4];
    #pragma unroll
    for (int i = 0; i < 4; i++)
        #pragma unroll
        for (int j = 0; j < 4; j++)
            #pragma unroll
            for (int r = 0; r < 4; r++) acc[i][j][r] = 0.f;

    const int KT = K >> 5;   // >= 3 for all calls
    #pragma unroll
    for (int i = 0; i < 3; i++) {
        gemm_issue_loads(sbase + i * STAGE_B, pAh, pAl, pBh, pBl, K, i << 5, tid);
        CP_COMMIT();
    }

    for (int kt = 0; kt < KT; kt++) {
        int rem = KT - 1 - kt;
        if (rem >= 2)      { CP_WAIT(2); }
        else if (rem == 1) { CP_WAIT(1); }
        else               { CP_WAIT(0); }
        __syncthreads();

        uint32_t st = sbase + (kt & 3) * STAGE_B;
        uint32_t sAh = st, sAl = st + TILE_B, sBh = st + 2*TILE_B, sBl = st + 3*TILE_B;

        #pragma unroll
        for (int kk = 0; kk < 2; kk++) {
            uint32_t ah[4][4], al[4][4];
            #pragma unroll
            for (int mi = 0; mi < 4; mi++) {
                uint32_t aoff = (uint32_t)(((wm * 64 + mi * 16) * TSTR + kk * 16) * 2);
                ldm4(ah[mi], sAh + aoff + laneA);
                ldm4(al[mi], sAl + aoff + laneA);
            }
            uint32_t bh[4][2], bl[4][2];
            #pragma unroll
            for (int nj2 = 0; nj2 < 2; nj2++) {
                uint32_t boff = (uint32_t)(((wn * 32 + nj2 * 16) * TSTR + kk * 16) * 2);
                uint32_t r[4];
                ldm4(r, sBh + boff + laneB);
                bh[nj2*2][0] = r[0]; bh[nj2*2][1] = r[1];
                bh[nj2*2+1][0] = r[2]; bh[nj2*2+1][1] = r[3];
                ldm4(r, sBl + boff + laneB);
                bl[nj2*2][0] = r[0]; bl[nj2*2][1] = r[1];
                bl[nj2*2+1][0] = r[2]; bl[nj2*2+1][1] = r[3];
            }
            #pragma unroll
            for (int mi = 0; mi < 4; mi++)
                #pragma unroll
                for (int nj = 0; nj < 4; nj++) {
                    mma_bf16(acc[mi][nj], ah[mi], bh[nj]);
                    mma_bf16(acc[mi][nj], ah[mi], bl[nj]);
                    mma_bf16(acc[mi][nj], al[mi], bh[nj]);
                }
        }

        if (kt + 3 < KT) {
            gemm_issue_loads(sbase + ((kt + 3) & 3) * STAGE_B,
                             pAh, pAl, pBh, pBl, K, (kt + 3) << 5, tid);
            CP_COMMIT();
        }
    }

    const int g = lane >> 2, tg = lane & 3;
    #pragma unroll
    for (int mi = 0; mi < 4; mi++) {
        int row = wm * 64 + mi * 16 + g;
        #pragma unroll
        for (int nj = 0; nj < 4; nj++) {
            int col = wn * 32 + nj * 8 + tg * 2;
            float* p0 = Ct + (size_t)row * N + col;
            float* p1 = p0 + (size_t)8 * N;
            p0[0] = acc[mi][nj][0]; p0[1] = acc[mi][nj][1];
            p1[0] = acc[mi][nj][2]; p1[1] = acc[mi][nj][3];
        }
    }
}

// Fused Q/K/V projection: grid (40, TOK/128). bx 0-31: Q; 32-35: K; 36-39: V.
__global__ void __launch_bounds__(256, 1)
gemm_qkv(const __nv_bfloat16* __restrict__ hh, const __nv_bfloat16* __restrict__ hl,
         const __nv_bfloat16* __restrict__ wqh, const __nv_bfloat16* __restrict__ wql,
         const __nv_bfloat16* __restrict__ wkh, const __nv_bfloat16* __restrict__ wkl,
         const __nv_bfloat16* __restrict__ wvh, const __nv_bfloat16* __restrict__ wvl,
         float* __restrict__ qb, float* __restrict__ kb, float* __restrict__ vb)
{
    extern __shared__ char smem[];
    const int bx = blockIdx.x;
    const int bm = blockIdx.y << 7;
    const __nv_bfloat16 *bhp, *blp;
    float* C; int bn, N;
    if (bx < 32)      { bhp = wqh; blp = wql; C = qb; bn = bx << 7;        N = QD;  }
    else if (bx < 36) { bhp = wkh; blp = wkl; C = kb; bn = (bx - 32) << 7; N = KVD; }
    else              { bhp = wvh; blp = wvl; C = vb; bn = (bx - 36) << 7; N = KVD; }
    gemm_core(hh + (size_t)bm * HID, hl + (size_t)bm * HID,
              bhp + (size_t)bn * HID, blp + (size_t)bn * HID,
              C + (size_t)bm * N + bn, N, HID, smem);
}

// Generic NT split GEMM (O-projection)
__global__ void __launch_bounds__(256, 1)
gemm_nt_split(const __nv_bfloat16* __restrict__ Ah, const __nv_bfloat16* __restrict__ Al,
              const __nv_bfloat16* __restrict__ Bh, const __nv_bfloat16* __restrict__ Bl,
              float* __restrict__ C, int N, int K)
{
    extern __shared__ char smem[];
    const int bm = blockIdx.y << 7;
    const int bn = blockIdx.x << 7;
    gemm_core(Ah + (size_t)bm * K, Al + (size_t)bm * K,
              Bh + (size_t)bn * K, Bl + (size_t)bn * K,
              C + (size_t)bm * N + bn, N, K, smem);
}

// ===========================================================================
// Flash attention: mma.sync split-bf16, FMA-pipe exp2, non-causal.
// Q-RoPE fused into the Q-load. Epilogue writes split bf16 hi/lo directly.
// ===========================================================================
#define FSTR 136
#define FA_Q_B (128*FSTR*2)
#define FA_T_B (64*FSTR*2)
#define FA_ST_B (4*FA_T_B)
#define FA_SMEM (2*FA_Q_B + 2*FA_ST_B)    // 208896

__device__ __forceinline__ void fa_load_kv(
    uint32_t stage, const __nv_bfloat16* __restrict__ Kh, const __nv_bfloat16* __restrict__ Kl,
    const __nv_bfloat16* __restrict__ Vh, const __nv_bfloat16* __restrict__ Vl,
    size_t rowbase, int kvoff, int tid)
{
    #pragma unroll
    for (int comp = 0; comp < 4; comp++) {
        const __nv_bfloat16* g = (comp == 0) ? Kh : (comp == 1) ? Kl : (comp == 2) ? Vh : Vl;
        #pragma unroll
        for (int jj = 0; jj < 4; jj++) {
            int cc = tid + (jj << 8);
            int row = cc >> 4, kc = cc & 15;
            cp_async16(stage + comp * FA_T_B + (uint32_t)(row * 272 + kc * 16),
                       g + (rowbase + row) * KVD + kvoff + kc * 8);
        }
    }
}

__global__ void __launch_bounds__(256, 1)
flash_attn_mma(const float* __restrict__ Q, const int* __restrict__ pos32,
               const __nv_bfloat16* __restrict__ Kh, const __nv_bfloat16* __restrict__ Kl,
               const __nv_bfloat16* __restrict__ Vh, const __nv_bfloat16* __restrict__ Vl,
               __nv_bfloat16* __restrict__ ah, __nv_bfloat16* __restrict__ al)
{
    extern __shared__ char smem[];
    uint32_t sb = smem_u32(smem);
    const uint32_t sQH = sb;
    const uint32_t sQL = sb + FA_Q_B;
    const uint32_t sST = sb + 2 * FA_Q_B;

    const int tid = threadIdx.x, lane = tid & 31, w = tid >> 5;
    const int bh = blockIdx.y, b = bh >> 5, h = bh & 31, kvh = h >> 3;
    const int q0 = blockIdx.x << 7;
    const int g = lane >> 2, t = lane & 3;

    // --- Q load + RoPE + scale(1/sqrt(d)*log2e) + hi/lo split into smem ---
    const float qsc = 0.08838834764831843f * 1.4426950408889634f;
    const float* Qg = Q + (size_t)(b * SEQ + q0) * QD + h * HD;
    const bool is64 = (pos32[1] == 0);
    #pragma unroll
    for (int i = 0; i < 8; i++) {
        int idx = tid + (i << 8);               // 0..2047
        int row = idx >> 4;                     // 0..127
        int d4  = (idx & 15) << 2;              // 0,4,...,60
        int tok = b * SEQ + q0 + row;
        int p = is64 ? pos32[2 * tok] : pos32[tok];
        float4 xa = *(const float4*)(Qg + (size_t)row * QD + d4);
        float4 xb = *(const float4*)(Qg + (size_t)row * QD + d4 + 64);
        float ya[4], yb[4];
        const float* x1 = &xa.x;
        const float* x2 = &xb.x;
        #pragma unroll
        for (int j = 0; j < 4; j++) {
            int d = d4 + j;
            float invf = powf(1.0e6f, -(float)d * (1.0f / 64.0f));
            float sv, cv;
            sincosf((float)p * invf, &sv, &cv);
            ya[j] = (x1[j] * cv - x2[j] * sv) * qsc;
            yb[j] = (x2[j] * cv + x1[j] * sv) * qsc;
        }
        uint32_t ha01 = cvt2bf(ya[1], ya[0]);
        uint32_t ha23 = cvt2bf(ya[3], ya[2]);
        uint32_t la01 = cvt2bf(ya[1] - bfhiF(ha01), ya[0] - bfloF(ha01));
        uint32_t la23 = cvt2bf(ya[3] - bfhiF(ha23), ya[2] - bfloF(ha23));
        uint32_t hb01 = cvt2bf(yb[1], yb[0]);
        uint32_t hb23 = cvt2bf(yb[3], yb[2]);
        uint32_t lb01 = cvt2bf(yb[1] - bfhiF(hb01), yb[0] - bfloF(hb01));
        uint32_t lb23 = cvt2bf(yb[3] - bfhiF(hb23), yb[2] - bfloF(hb23));
        uint32_t off1 = (uint32_t)(row * 272 + d4 * 2);
        uint32_t off2 = (uint32_t)(row * 272 + (d4 + 64) * 2);
        *(uint2*)(smem + (sQH - sb) + off1) = make_uint2(ha01, ha23);
        *(uint2*)(smem + (sQL - sb) + off1) = make_uint2(la01, la23);
        *(uint2*)(smem + (sQH - sb) + off2) = make_uint2(hb01, hb23);
        *(uint2*)(smem + (sQL - sb) + off2) = make_uint2(lb01, lb23);
    }

    float m0 = -1e30f, m1 = -1e30f, l0 = 0.f, l1 = 0.f;
    float o[16][4];
    #pragma unroll
    for (int nd = 0; nd < 16; nd++)
        #pragma unroll
        for (int c = 0; c < 4; c++) o[nd][c] = 0.f;

    const size_t kvbase = (size_t)b * SEQ;
    const int kvoff = kvh * HD;

    const uint32_t lA = (uint32_t)(((lane & 15) * FSTR + ((lane >> 4) << 3)) * 2);
    const uint32_t lB = (uint32_t)((((lane & 7) + ((lane >> 4) << 3)) * FSTR
                                    + (((lane >> 3) & 1) << 3)) * 2);
    const uint32_t lV = (uint32_t)((((lane & 7) + (((lane >> 3) & 1) << 3)) * FSTR
                                    + (((lane >> 4) & 1) << 3)) * 2);

    fa_load_kv(sST, Kh, Kl, Vh, Vl, kvbase, kvoff, tid);
    CP_COMMIT();

    for (int kt = 0; kt < SEQ / 64; kt++) {
        if (kt + 1 < SEQ / 64) {
            fa_load_kv(sST + ((kt + 1) & 1) * FA_ST_B, Kh, Kl, Vh, Vl,
                       kvbase + (size_t)(kt + 1) * 64, kvoff, tid);
            CP_COMMIT();
            CP_WAIT(1);
        } else {
            CP_WAIT(0);
        }
        __syncthreads();

        const uint32_t st = sST + (kt & 1) * FA_ST_B;
        const uint32_t sKH = st, sKL = st + FA_T_B, sVH = st + 2*FA_T_B, sVL = st + 3*FA_T_B;

        float s[8][4];
        #pragma unroll
        for (int j = 0; j < 8; j++)
            #pragma unroll
            for (int c = 0; c < 4; c++) s[j][c] = 0.f;

        #pragma unroll
        for (int kk = 0; kk < 8; kk++) {
            uint32_t qh[4], ql[4];
            uint32_t qoff = (uint32_t)((w * 16 * FSTR + kk * 16) * 2);
            ldm4(qh, sQH + qoff + lA);
            ldm4(ql, sQL + qoff + lA);
            #pragma unroll
            for (int nj2 = 0; nj2 < 4; nj2++) {
                uint32_t koff = (uint32_t)((nj2 * 16 * FSTR + kk * 16) * 2);
                uint32_t rh[4], rl[4];
                ldm4(rh, sKH + koff + lB);
                ldm4(rl, sKL + koff + lB);
                mma_bf16(s[nj2*2],   qh, rh);     mma_bf16(s[nj2*2],   qh, rl);
                mma_bf16(s[nj2*2],   ql, rh);
                mma_bf16(s[nj2*2+1], qh, rh + 2); mma_bf16(s[nj2*2+1], qh, rl + 2);
                mma_bf16(s[nj2*2+1], ql, rh + 2);
            }
        }

        float mx0 = -1e30f, mx1 = -1e30f;
        #pragma unroll
        for (int j = 0; j < 8; j++) {
            mx0 = fmaxf(mx0, fmaxf(s[j][0], s[j][1]));
            mx1 = fmaxf(mx1, fmaxf(s[j][2], s[j][3]));
        }
        mx0 = fmaxf(mx0, __shfl_xor_sync(0xffffffffu, mx0, 1));
        mx0 = fmaxf(mx0, __shfl_xor_sync(0xffffffffu, mx0, 2));
        mx1 = fmaxf(mx1, __shfl_xor_sync(0xffffffffu, mx1, 1));
        mx1 = fmaxf(mx1, __shfl_xor_sync(0xffffffffu, mx1, 2));
        float mn0 = fmaxf(m0, mx0), mn1 = fmaxf(m1, mx1);
        float al0 = fast_exp2(m0 - mn0), al1 = fast_exp2(m1 - mn1);
        m0 = mn0; m1 = mn1;

        uint32_t ph[4][4], pl[4][4];
        float sum0 = 0.f, sum1 = 0.f;
        #pragma unroll
        for (int j = 0; j < 8; j++) {
            float p00 = fast_exp2(s[j][0] - mn0);
            float p01 = fast_exp2(s[j][1] - mn0);
            float p10 = fast_exp2(s[j][2] - mn1);
            float p11 = fast_exp2(s[j][3] - mn1);
            sum0 += p00 + p01; sum1 += p10 + p11;
            uint32_t hA = cvt2bf(p01, p00);
            uint32_t hB = cvt2bf(p11, p10);
            uint32_t lAp = cvt2bf(p01 - bfhiF(hA), p00 - bfloF(hA));
            uint32_t lBp = cvt2bf(p11 - bfhiF(hB), p10 - bfloF(hB));
            int kk2 = j >> 1, hf = (j & 1) << 1;
            ph[kk2][hf]     = hA;  ph[kk2][hf + 1] = hB;
            pl[kk2][hf]     = lAp; pl[kk2][hf + 1] = lBp;
        }
        sum0 += __shfl_xor_sync(0xffffffffu, sum0, 1);
        sum0 += __shfl_xor_sync(0xffffffffu, sum0, 2);
        sum1 += __shfl_xor_sync(0xffffffffu, sum1, 1);
        sum1 += __shfl_xor_sync(0xffffffffu, sum1, 2);
        l0 = l0 * al0 + sum0;
        l1 = l1 * al1 + sum1;
        #pragma unroll
        for (int nd = 0; nd < 16; nd++) {
            o[nd][0] *= al0; o[nd][1] *= al0;
            o[nd][2] *= al1; o[nd][3] *= al1;
        }

        #pragma unroll
        for (int kk2 = 0; kk2 < 4; kk2++) {
            #pragma unroll
            for (int ndp = 0; ndp < 8; ndp++) {
                uint32_t voff = (uint32_t)((kk2 * 16 * FSTR + ndp * 16) * 2);
                uint32_t vh[4], vl[4];
                ldm4t(vh, sVH + voff + lV);
                ldm4t(vl, sVL + voff + lV);
                mma_bf16(o[ndp*2],   ph[kk2], vh);     mma_bf16(o[ndp*2],   ph[kk2], vl);
                mma_bf16(o[ndp*2],   pl[kk2], vh);
                mma_bf16(o[ndp*2+1], ph[kk2], vh + 2); mma_bf16(o[ndp*2+1], ph[kk2], vl + 2);
                mma_bf16(o[ndp*2+1], pl[kk2], vh + 2);
            }
        }
        __syncthreads();
    }

    float il0 = 1.f / l0, il1 = 1.f / l1;
    size_t rbase = (size_t)(b * SEQ + q0 + w * 16 + g) * QD + h * HD;
    __nv_bfloat16* AH = ah + rbase;
    __nv_bfloat16* AL = al + rbase;
    #pragma unroll
    for (int nd = 0; nd < 16; nd++) {
        int col = nd * 8 + t * 2;
        float a0 = o[nd][0] * il0, a1 = o[nd][1] * il0;
        uint32_t hp = cvt2bf(a1, a0);
        uint32_t lp = cvt2bf(a1 - bfhiF(hp), a0 - bfloF(hp));
        *(uint32_t*)(AH + col) = hp;
        *(uint32_t*)(AL + col) = lp;
        float b0 = o[nd][2] * il1, b1 = o[nd][3] * il1;
        hp = cvt2bf(b1, b0);
        lp = cvt2bf(b1 - bfhiF(hp), b0 - bfloF(hp));
        *(uint32_t*)(AH + (size_t)8 * QD + col) = hp;
        *(uint32_t*)(AL + (size_t)8 * QD + col) = lp;
    }
}

// ---------------------------------------------------------------------------
extern "C" void kernel_launch(void* const* d_in, const int* in_sizes, int n_in,
                              void* d_out, int out_size)
{
    const float* hidden = (const float*)d_in[0];
    const int*   pos    = (const int*)d_in[1];
    const float* Wq     = (const float*)d_in[2];
    const float* Wk     = (const float*)d_in[3];
    const float* Wv     = (const float*)d_in[4];
    const float* Wo     = (const float*)d_in[5];
    float*       out    = (float*)d_out;

    float *qb, *kb, *vb;
    cudaGetSymbolAddress((void**)&qb, g_q);
    cudaGetSymbolAddress((void**)&kb, g_k);
    cudaGetSymbolAddress((void**)&vb, g_v);
    __nv_bfloat16 *hh,*hl,*wqh,*wql,*wkh,*wkl,*wvh,*wvl,*woh,*wol,*ah,*al,*kh,*kl,*vh,*vl;
    cudaGetSymbolAddress((void**)&hh,  g_hh);  cudaGetSymbolAddress((void**)&hl,  g_hl);
    cudaGetSymbolAddress((void**)&wqh, g_wqh); cudaGetSymbolAddress((void**)&wql, g_wql);
    cudaGetSymbolAddress((void**)&wkh, g_wkh); cudaGetSymbolAddress((void**)&wkl, g_wkl);
    cudaGetSymbolAddress((void**)&wvh, g_wvh); cudaGetSymbolAddress((void**)&wvl, g_wvl);
    cudaGetSymbolAddress((void**)&woh, g_woh); cudaGetSymbolAddress((void**)&wol, g_wol);
    cudaGetSymbolAddress((void**)&ah,  g_ah);  cudaGetSymbolAddress((void**)&al,  g_al);
    cudaGetSymbolAddress((void**)&kh,  g_kh);  cudaGetSymbolAddress((void**)&kl,  g_kl);
    cudaGetSymbolAddress((void**)&vh,  g_vh);  cudaGetSymbolAddress((void**)&vl,  g_vl);

    cudaFuncSetAttribute(gemm_qkv, cudaFuncAttributeMaxDynamicSharedMemorySize, GEMM_SMEM);
    cudaFuncSetAttribute(gemm_nt_split, cudaFuncAttributeMaxDynamicSharedMemorySize, GEMM_SMEM);
    cudaFuncSetAttribute(flash_attn_mma, cudaFuncAttributeMaxDynamicSharedMemorySize, FA_SMEM);

    // All input/weight splits in one launch
    split_all_kernel<<<(SPL_N4 + 255)/256, 256>>>(hidden, Wq, Wk, Wv, Wo,
                                                  hh, hl, wqh, wql, wkh, wkl,
                                                  wvh, wvl, woh, wol);

    // Fused Q/K/V projections (128x128 tiles, 4-stage)
    gemm_qkv<<<dim3(40, TOK/128), 256, GEMM_SMEM>>>(hh, hl, wqh, wql, wkh, wkl, wvh, wvl,
                                                    qb, kb, vb);

    // K rope+split and V split in one launch
    prep_kv<<<(PK_N1 + 255)/256, 256>>>(kb, vb, pos, kh, kl, vh, vl);

    // Flash attention (Q rope fused) -> split bf16 output
    flash_attn_mma<<<dim3(SEQ/128, BATCH*NH), 256, FA_SMEM>>>(qb, pos, kh, kl, vh, vl, ah, al);

    // O projection (128x128 tiles)
    gemm_nt_split<<<dim3(HID/128, TOK/128), 256, GEMM_SMEM>>>(ah, al, woh, wol, out, HID, QD);
}